// round 15
// baseline (speedup 1.0000x reference)
#include <cuda_runtime.h>
#include <cuda_bf16.h>
#include <cstdint>

// ---------------- problem constants ----------------
#define BATCH   1024
#define NSAMP   8
#define KDIM    6
#define NITERS  20
#define KZ4     10          // conv4 split-K factor

// ---------------- scratch (device globals; no allocs allowed) ----------------
__device__ float g_act1[BATCH * 32 * 30 * 30];
__device__ float g_act2[BATCH * 64 * 13 * 13];
__device__ float g_act3[BATCH * 128 * 5 * 5];
__device__ float g_featp[KZ4 * BATCH * 256];
__device__ float g_logalpha[BATCH * 36];

// ============================================================================
// helpers
// ============================================================================
__device__ __forceinline__ uint32_t f2tf32(float f) {
    uint32_t r;
    asm("cvt.rna.tf32.f32 %0, %1;" : "=r"(r) : "f"(f));
    return r;
}
__device__ __forceinline__ void mma_tf32(float* d, const uint32_t* a, const uint32_t* b) {
    asm volatile(
        "mma.sync.aligned.m16n8k8.row.col.f32.tf32.tf32.f32 "
        "{%0,%1,%2,%3}, {%4,%5,%6,%7}, {%8,%9}, {%0,%1,%2,%3};"
        : "+f"(d[0]), "+f"(d[1]), "+f"(d[2]), "+f"(d[3])
        : "r"(a[0]), "r"(a[1]), "r"(a[2]), "r"(a[3]), "r"(b[0]), "r"(b[1]));
}
__device__ __forceinline__ uint32_t s2u(const void* p) {
    uint32_t a;
    asm("{ .reg .u64 t; cvta.to.shared.u64 t, %1; cvt.u32.u64 %0, t; }" : "=r"(a) : "l"(p));
    return a;
}
#define LDMX4(r, addr) \
    asm volatile("ldmatrix.sync.aligned.m8n8.x4.shared.b16 {%0,%1,%2,%3}, [%4];" \
        : "=r"((r)[0]), "=r"((r)[1]), "=r"((r)[2]), "=r"((r)[3]) : "r"(addr))
#define LDMX2(r, addr) \
    asm volatile("ldmatrix.sync.aligned.m8n8.x2.shared.b16 {%0,%1}, [%2];" \
        : "=r"((r)[0]), "=r"((r)[1]) : "r"(addr))

// pitch 60 (R12-verified conflict-free for build + row-spaced ldmatrix)
#define PITCH 60

// no-op kernel: keeps the ncu profiled-launch slot on conv2_mma
__global__ void noop_kernel() {}

// ============================================================================
// conv1 (scalar fp32, proven): [B,3,64,64] -> [B,32,30,30]. 16 oc/CTA.
// ============================================================================
__global__ __launch_bounds__(256, 2) void conv1_kernel(
    const float* __restrict__ im, const float* __restrict__ w1,
    const float* __restrict__ b1)
{
    __shared__ float s_in[64 * 64];
    __shared__ float s_w[16 * 75];

    const int b   = blockIdx.x;
    const int oc0 = blockIdx.y * 16;
    const int t   = threadIdx.x;

    for (int i = t; i < 1200; i += 256) s_w[i] = w1[oc0 * 75 + i];

    float acc[4][16];
#pragma unroll
    for (int i = 0; i < 4; i++)
#pragma unroll
        for (int o = 0; o < 16; o++) acc[i][o] = 0.f;

    int bo[4]; bool val[4];
#pragma unroll
    for (int i = 0; i < 4; i++) {
        int p = t + 256 * i;
        val[i] = (p < 900);
        int oy = p / 30, ox = p % 30;
        bo[i] = val[i] ? (2 * oy * 64 + 2 * ox) : 0;
    }

#pragma unroll 1
    for (int c = 0; c < 3; c++) {
        __syncthreads();
        const float4* src = reinterpret_cast<const float4*>(im + (b * 3 + c) * 4096);
        float4* dst = reinterpret_cast<float4*>(s_in);
        for (int e = t; e < 1024; e += 256) dst[e] = src[e];
        __syncthreads();

#pragma unroll 1
        for (int ky = 0; ky < 5; ky++) {
#pragma unroll
            for (int kx = 0; kx < 5; kx++) {
                float w16[16];
#pragma unroll
                for (int o = 0; o < 16; o++)
                    w16[o] = s_w[o * 75 + c * 25 + ky * 5 + kx];
#pragma unroll
                for (int i = 0; i < 4; i++) {
                    float v = s_in[bo[i] + ky * 64 + kx];
#pragma unroll
                    for (int o = 0; o < 16; o++) acc[i][o] += v * w16[o];
                }
            }
        }
    }

#pragma unroll
    for (int o = 0; o < 16; o++) {
        float bias = b1[oc0 + o];
#pragma unroll
        for (int i = 0; i < 4; i++) {
            int p = t + 256 * i;
            if (val[i])
                g_act1[(b * 32 + oc0 + o) * 900 + p] = fmaxf(acc[i][o] + bias, 0.f);
        }
    }
}

// ============================================================================
// conv2 via tf32 mma.sync (R12 structure) + ldmatrix fragment loads.
// 2 ch/chunk (K=56, 7 k8-steps), 16 chunks. grid 1024, block 256 (4m x 2n).
// smem (u32): A[192*60] B[64*60] ph[1800] = 68640 B (opt-in)
// ============================================================================
#define C2_A  0
#define C2_B  (192*PITCH)               // 11520
#define C2_P  (C2_B + 64*PITCH)         // 15360
#define C2_SMEM_ELEMS (C2_P + 1800)     // 17160 u32 = 68640 B

__global__ __launch_bounds__(256, 2) void conv2_mma(
    const float* __restrict__ w2, const float* __restrict__ b2)
{
    extern __shared__ uint32_t s2[];
    uint32_t* A  = s2 + C2_A;
    uint32_t* B  = s2 + C2_B;
    uint32_t* ph = s2 + C2_P;

    const int b = blockIdx.x, t = threadIdx.x;
    const int wid = t >> 5, lane = t & 31, g = lane >> 2, tq = lane & 3;
    const int wm = wid >> 1, wn = wid & 1;   // 4m x 2n

    for (int i = t; i < C2_P; i += 256) s2[i] = 0u;

    // ldmatrix per-lane addresses (hoisted): A x4 subs (row, row+8) x (col 0, 4)
    const uint32_t sbase = s2u(s2);
    const int sub = lane >> 3, ri = lane & 7;
    uint32_t aAddr[3];
#pragma unroll
    for (int mt = 0; mt < 3; mt++) {
        const int row = wm * 48 + mt * 16 + ((sub & 1) << 3) + ri;
        const int col = (sub & 2) ? 4 : 0;
        aAddr[mt] = sbase + (uint32_t)((C2_A + row * PITCH + col) * 4);
    }
    uint32_t bAddr[4];
    const int bsub = (lane >> 3) & 1;
#pragma unroll
    for (int nt = 0; nt < 4; nt++) {
        const int n = wn * 32 + nt * 8 + ri;
        const int col = bsub ? 4 : 0;
        bAddr[nt] = sbase + (uint32_t)((C2_B + n * PITCH + col) * 4);
    }

    float acc[3][4][4];
#pragma unroll
    for (int mt = 0; mt < 3; mt++)
#pragma unroll
        for (int nt = 0; nt < 4; nt++)
#pragma unroll
            for (int i = 0; i < 4; i++) acc[mt][nt][i] = 0.f;

    const float* src = g_act1 + b * 32 * 900;
    float4 pf0 = make_float4(0.f,0.f,0.f,0.f), pf1 = pf0;
    if (t < 225) {
        pf0 = reinterpret_cast<const float4*>(src)[t];
        pf1 = reinterpret_cast<const float4*>(src)[t + 225];
    }

#pragma unroll 1
    for (int cc = 0; cc < 16; cc++) {
        if (t < 225) {
            ph[4*t+0] = f2tf32(pf0.x); ph[4*t+1] = f2tf32(pf0.y);
            ph[4*t+2] = f2tf32(pf0.z); ph[4*t+3] = f2tf32(pf0.w);
            const int u = 4 * (t + 225);
            ph[u+0] = f2tf32(pf1.x); ph[u+1] = f2tf32(pf1.y);
            ph[u+2] = f2tf32(pf1.z); ph[u+3] = f2tf32(pf1.w);
        }
        __syncthreads();

        if (cc + 1 < 16 && t < 225) {
            const float4* nsrc = reinterpret_cast<const float4*>(src + (cc + 1) * 1800);
            pf0 = nsrc[t];
            pf1 = nsrc[t + 225];
        }

        if (t < 169) {
            const int ib = (t / 13) * 60 + (t % 13) * 2;
            uint32_t* Arow = &A[t * PITCH];
#pragma unroll
            for (int c2 = 0; c2 < 2; c2++)
#pragma unroll
                for (int k = 0; k < 25; k++)
                    Arow[c2 * 25 + k] = ph[c2 * 900 + ib + (k / 5) * 30 + (k % 5)];
        } else if (t < 233) {
            const int oc = t - 169;
            const float* ws = w2 + oc * 800 + cc * 50;
            uint32_t* Brow = &B[oc * PITCH];
#pragma unroll
            for (int k = 0; k < 50; k++)
                Brow[k] = f2tf32(ws[k]);
        }
        __syncthreads();

#pragma unroll
        for (int ks = 0; ks < 7; ks++) {
            const uint32_t koff = (uint32_t)(ks * 32);   // 8 words * 4B
            uint32_t a[3][4], bb[4][2];
#pragma unroll
            for (int mt = 0; mt < 3; mt++) LDMX4(a[mt], aAddr[mt] + koff);
#pragma unroll
            for (int nt = 0; nt < 4; nt++) LDMX2(bb[nt], bAddr[nt] + koff);
#pragma unroll
            for (int mt = 0; mt < 3; mt++)
#pragma unroll
                for (int nt = 0; nt < 4; nt++)
                    mma_tf32(acc[mt][nt], a[mt], bb[nt]);
        }
        __syncthreads();
    }

    float* dst = g_act2 + b * 64 * 169;
#pragma unroll
    for (int mt = 0; mt < 3; mt++) {
        const int r0 = wm * 48 + mt * 16 + g;
        const int r1 = r0 + 8;
#pragma unroll
        for (int nt = 0; nt < 4; nt++) {
            const int n0 = wn * 32 + nt * 8 + 2 * tq;
            const float bi0 = b2[n0], bi1 = b2[n0 + 1];
            if (r0 < 169) {
                dst[n0 * 169 + r0]       = fmaxf(acc[mt][nt][0] + bi0, 0.f);
                dst[(n0 + 1) * 169 + r0] = fmaxf(acc[mt][nt][1] + bi1, 0.f);
            }
            if (r1 < 169) {
                dst[n0 * 169 + r1]       = fmaxf(acc[mt][nt][2] + bi0, 0.f);
                dst[(n0 + 1) * 169 + r1] = fmaxf(acc[mt][nt][3] + bi1, 0.f);
            }
        }
    }
}

// ============================================================================
// conv3 via tf32 mma.sync (R12 structure) + ldmatrix. 5 img/CTA, 32 chunks.
// grid 205, block 256 (2m x 4n; warp tile 64x32).
// smem (u32): A[128*60] B[128*60] ph[1690] = 68200 B (opt-in)
// ============================================================================
#define C3_A  0
#define C3_B  (128*PITCH)               // 7680
#define C3_P  (C3_B + 128*PITCH)        // 15360
#define C3_SMEM_ELEMS (C3_P + 1690)     // 17050 u32 = 68200 B

__global__ __launch_bounds__(256, 2) void conv3_mma(
    const float* __restrict__ w3, const float* __restrict__ b3)
{
    extern __shared__ uint32_t s3[];
    uint32_t* A  = s3 + C3_A;
    uint32_t* B  = s3 + C3_B;
    uint32_t* ph = s3 + C3_P;

    const int t = threadIdx.x;
    const int wid = t >> 5, lane = t & 31, g = lane >> 2, tq = lane & 3;
    const int wm = wid >> 2, wn = wid & 3;   // 2m x 4n
    const int b0 = blockIdx.x * 5;
    const int nimg = (BATCH - b0 < 5) ? (BATCH - b0) : 5;

    for (int i = t; i < C3_P; i += 256) s3[i] = 0u;

    const uint32_t sbase = s2u(s3);
    const int sub = lane >> 3, ri = lane & 7;
    uint32_t aAddr[4];
#pragma unroll
    for (int mt = 0; mt < 4; mt++) {
        const int row = wm * 64 + mt * 16 + ((sub & 1) << 3) + ri;
        const int col = (sub & 2) ? 4 : 0;
        aAddr[mt] = sbase + (uint32_t)((C3_A + row * PITCH + col) * 4);
    }
    uint32_t bAddr[4];
    const int bsub = (lane >> 3) & 1;
#pragma unroll
    for (int nt = 0; nt < 4; nt++) {
        const int n = wn * 32 + nt * 8 + ri;
        const int col = bsub ? 4 : 0;
        bAddr[nt] = sbase + (uint32_t)((C3_B + n * PITCH + col) * 4);
    }

    float acc[4][4][4];
#pragma unroll
    for (int mt = 0; mt < 4; mt++)
#pragma unroll
        for (int nt = 0; nt < 4; nt++)
#pragma unroll
            for (int i = 0; i < 4; i++) acc[mt][nt][i] = 0.f;

    float pf[7];
    int pfil[7], pfc2[7], pfidx[7]; bool pfv[7];
#pragma unroll
    for (int k = 0; k < 7; k++) {
        const int i = t + 256 * k;
        pfv[k]   = (i < 1690);
        const int il = pfv[k] ? (i / 338) : 0;
        const int r  = pfv[k] ? (i % 338) : 0;
        pfil[k]  = il;
        pfc2[k]  = r / 169;
        pfidx[k] = r % 169;
        pfv[k]   = pfv[k] && (il < nimg);
        pf[k] = pfv[k] ? g_act2[((b0 + il) * 64 + pfc2[k]) * 169 + pfidx[k]] : 0.f;
    }

#pragma unroll 1
    for (int cc = 0; cc < 32; cc++) {
#pragma unroll
        for (int k = 0; k < 7; k++) {
            const int i = t + 256 * k;
            if (i < 1690) ph[i] = f2tf32(pf[k]);
        }
        __syncthreads();

        if (cc + 1 < 32) {
#pragma unroll
            for (int k = 0; k < 7; k++)
                if (pfv[k])
                    pf[k] = g_act2[((b0 + pfil[k]) * 64 + (cc + 1) * 2 + pfc2[k]) * 169 + pfidx[k]];
        }

        if (t < 125) {
            const int il = t / 25, p = t % 25;
            if (il < nimg) {
                const int pb = (p / 5) * 26 + (p % 5) * 2;
                uint32_t* Arow = &A[t * PITCH];
#pragma unroll
                for (int c2 = 0; c2 < 2; c2++)
#pragma unroll
                    for (int k = 0; k < 25; k++)
                        Arow[c2 * 25 + k] =
                            ph[il * 338 + c2 * 169 + pb + (k / 5) * 13 + (k % 5)];
            }
        } else if (t < 253) {
            const int oc = t - 125;
            const float* ws = w3 + oc * 1600 + cc * 50;
            uint32_t* Brow = &B[oc * PITCH];
#pragma unroll
            for (int k = 0; k < 50; k++)
                Brow[k] = f2tf32(ws[k]);
        }
        __syncthreads();

#pragma unroll
        for (int ks = 0; ks < 7; ks++) {
            const uint32_t koff = (uint32_t)(ks * 32);
            uint32_t a[4][4], bb[4][2];
#pragma unroll
            for (int mt = 0; mt < 4; mt++) LDMX4(a[mt], aAddr[mt] + koff);
#pragma unroll
            for (int nt = 0; nt < 4; nt++) LDMX2(bb[nt], bAddr[nt] + koff);
#pragma unroll
            for (int mt = 0; mt < 4; mt++)
#pragma unroll
                for (int nt = 0; nt < 4; nt++)
                    mma_tf32(acc[mt][nt], a[mt], bb[nt]);
        }
        __syncthreads();
    }

#pragma unroll
    for (int mt = 0; mt < 4; mt++) {
#pragma unroll
        for (int nt = 0; nt < 4; nt++) {
            const int n0 = wn * 32 + nt * 8 + 2 * tq;
            const float bi0 = b3[n0], bi1 = b3[n0 + 1];
#pragma unroll
            for (int half = 0; half < 2; half++) {
                const int r = wm * 64 + mt * 16 + g + half * 8;
                if (r < 125) {
                    const int il = r / 25, pp = r % 25;
                    if (il < nimg) {
                        float* o = g_act3 + ((b0 + il) * 128) * 25 + pp;
                        o[n0 * 25]       = fmaxf(acc[mt][nt][half * 2 + 0] + bi0, 0.f);
                        o[(n0 + 1) * 25] = fmaxf(acc[mt][nt][half * 2 + 1] + bi1, 0.f);
                    }
                }
            }
        }
    }
}

// ============================================================================
// conv4: split-K x10 scalar GEMM partials. grid (16,4,10), chunk 320.
// ============================================================================
__global__ __launch_bounds__(256) void conv4_kernel(
    const float* __restrict__ w4)
{
    __shared__ float s_a[32 * 68];
    __shared__ float s_w[32 * 68];

    const int bm = blockIdx.x * 64;
    const int bn = blockIdx.y * 64;
    const int kz = blockIdx.z;
    const int t  = threadIdx.x;
    const int tx = t & 15;
    const int ty = t >> 4;

    const float* Ag = g_act3;

    float acc[4][4];
#pragma unroll
    for (int i = 0; i < 4; i++)
#pragma unroll
        for (int j = 0; j < 4; j++) acc[i][j] = 0.f;

#pragma unroll 1
    for (int k0 = kz * 320; k0 < kz * 320 + 320; k0 += 32) {
        __syncthreads();
        for (int e = t; e < 2048; e += 256) {
            int r = e >> 5, kk = e & 31;
            s_a[kk * 68 + r] = Ag[(bm + r) * 3200 + k0 + kk];
            s_w[kk * 68 + r] = w4[(bn + r) * 3200 + k0 + kk];
        }
        __syncthreads();

#pragma unroll 4
        for (int kk = 0; kk < 32; kk++) {
            float4 av = *reinterpret_cast<const float4*>(&s_a[kk * 68 + ty * 4]);
            float4 wv = *reinterpret_cast<const float4*>(&s_w[kk * 68 + tx * 4]);
            float a[4] = {av.x, av.y, av.z, av.w};
            float w[4] = {wv.x, wv.y, wv.z, wv.w};
#pragma unroll
            for (int i = 0; i < 4; i++)
#pragma unroll
                for (int j = 0; j < 4; j++) acc[i][j] += a[i] * w[j];
        }
    }

    float* dst = g_featp + kz * (BATCH * 256);
#pragma unroll
    for (int i = 0; i < 4; i++)
#pragma unroll
        for (int j = 0; j < 4; j++)
            dst[(bm + ty * 4 + i) * 256 + (bn + tx * 4 + j)] = acc[i][j];
}

// ============================================================================
// head: feat = relu(sum_z partials + b4); latent; log_alpha; stopping softmax
// ============================================================================
__global__ __launch_bounds__(256) void head_kernel(
    const float* __restrict__ b4,
    const float* __restrict__ enc_w, const float* __restrict__ enc_b,
    const float* __restrict__ sink_w, const float* __restrict__ sink_b,
    const float* __restrict__ mask_w, const float* __restrict__ mask_b,
    float* __restrict__ out_stop)
{
    __shared__ float s_encw[16 * 257];
    __shared__ float s_feat[16][256];
    __shared__ float s_sw[576], s_sb[36], s_mw[96], s_mb[6];
    __shared__ float s_lat[16][16];

    const int t  = threadIdx.x;
    const int b0 = blockIdx.x * 16;

    for (int e = t; e < 4096; e += 256) {
        int l = e >> 8, i = e & 255;
        s_encw[l * 257 + i] = enc_w[e];
        float v = b4[i];
#pragma unroll
        for (int z = 0; z < KZ4; z++)
            v += g_featp[z * (BATCH * 256) + (b0 + l) * 256 + i];
        s_feat[l][i] = fmaxf(v, 0.f);
    }
    for (int e = t; e < 576; e += 256) s_sw[e] = sink_w[e];
    if (t < 36) s_sb[t] = sink_b[t];
    for (int e = t; e < 96; e += 256) s_mw[e] = mask_w[e];
    if (t < 6) s_mb[t] = mask_b[t];
    __syncthreads();

    const int bl = t >> 4;
    const int l  = t & 15;
    const int b  = b0 + bl;

    float lat = enc_b[l];
#pragma unroll 8
    for (int i = 0; i < 256; i++)
        lat += s_feat[bl][i] * s_encw[l * 257 + i];
    s_lat[bl][l] = lat;
    __syncthreads();

    for (int rr = l; rr < 36; rr += 16) {
        float la = s_sb[rr];
#pragma unroll
        for (int i = 0; i < 16; i++) la += s_lat[bl][i] * s_sw[rr * 16 + i];
        g_logalpha[b * 36 + rr] = la;
    }

    if (l == 0) {
        float lg[6];
        float mx = -1e30f;
#pragma unroll
        for (int k = 0; k < 6; k++) {
            float v = s_mb[k];
#pragma unroll
            for (int i = 0; i < 16; i++) v += s_lat[bl][i] * s_mw[k * 16 + i];
            lg[k] = v;
            mx = fmaxf(mx, v);
        }
        float sum = 0.f;
#pragma unroll
        for (int k = 0; k < 6; k++) { lg[k] = __expf(lg[k] - mx); sum += lg[k]; }
        float inv = 1.f / sum;
#pragma unroll
        for (int k = 0; k < 6; k++) out_stop[b * 6 + k] = lg[k] * inv;
    }
}

// ============================================================================
// sinkhorn: one thread per 6x6 matrix, grid 64 x block 128
// ============================================================================
__global__ __launch_bounds__(128) void sinkhorn_kernel(
    const float* __restrict__ gn, const float* __restrict__ seq,
    float* __restrict__ out_ordered)
{
    const int m = blockIdx.x * 128 + threadIdx.x;
    const int b = m & (BATCH - 1);

    float la[36];
#pragma unroll
    for (int i = 0; i < 36; i++)
        la[i] = g_logalpha[b * 36 + i] + gn[m * 36 + i];

    float sq[6];
#pragma unroll
    for (int j = 0; j < 6; j++) sq[j] = seq[b * 6 + j];

#pragma unroll 1
    for (int it = 0; it < NITERS; it++) {
#pragma unroll
        for (int j = 0; j < 6; j++) {
            float mx = la[j * 6];
#pragma unroll
            for (int k = 1; k < 6; k++) mx = fmaxf(mx, la[j * 6 + k]);
            float s = 0.f;
#pragma unroll
            for (int k = 0; k < 6; k++) s += __expf(la[j * 6 + k] - mx);
            float lse = mx + __logf(s);
#pragma unroll
            for (int k = 0; k < 6; k++) la[j * 6 + k] -= lse;
        }
#pragma unroll
        for (int k = 0; k < 6; k++) {
            float mx = la[k];
#pragma unroll
            for (int j = 1; j < 6; j++) mx = fmaxf(mx, la[j * 6 + k]);
            float s = 0.f;
#pragma unroll
            for (int j = 0; j < 6; j++) s += __expf(la[j * 6 + k] - mx);
            float lse = mx + __logf(s);
#pragma unroll
            for (int j = 0; j < 6; j++) la[j * 6 + k] -= lse;
        }
    }

#pragma unroll
    for (int k = 0; k < 6; k++) {
        float o = 0.f;
#pragma unroll
        for (int j = 0; j < 6; j++) o += __expf(la[j * 6 + k]) * sq[j];
        out_ordered[m * 6 + k] = o;
    }
}

// ============================================================================
extern "C" void kernel_launch(void* const* d_in, const int* in_sizes, int n_in,
                              void* d_out, int out_size)
{
    const float* seq    = (const float*)d_in[0];
    const float* im     = (const float*)d_in[1];
    const float* gn     = (const float*)d_in[2];
    const float* w1     = (const float*)d_in[3];
    const float* b1     = (const float*)d_in[4];
    const float* w2     = (const float*)d_in[5];
    const float* b2     = (const float*)d_in[6];
    const float* w3     = (const float*)d_in[7];
    const float* b3     = (const float*)d_in[8];
    const float* w4     = (const float*)d_in[9];
    const float* b4     = (const float*)d_in[10];
    const float* enc_w  = (const float*)d_in[11];
    const float* enc_b  = (const float*)d_in[12];
    const float* sink_w = (const float*)d_in[13];
    const float* sink_b = (const float*)d_in[14];
    const float* mask_w = (const float*)d_in[15];
    const float* mask_b = (const float*)d_in[16];

    float* out = (float*)d_out;
    float* out_ordered = out;                         // [8192*6]
    float* out_stop    = out + NSAMP * BATCH * KDIM;  // [1024*6]

    cudaFuncSetAttribute(conv2_mma, cudaFuncAttributeMaxDynamicSharedMemorySize,
                         C2_SMEM_ELEMS * 4);
    cudaFuncSetAttribute(conv3_mma, cudaFuncAttributeMaxDynamicSharedMemorySize,
                         C3_SMEM_ELEMS * 4);

    conv1_kernel<<<dim3(BATCH, 2), 256>>>(im, w1, b1);
    // keep the ncu profiled slot on conv2_mma
    noop_kernel<<<1, 32>>>();
    noop_kernel<<<1, 32>>>();
    conv2_mma<<<BATCH, 256, C2_SMEM_ELEMS * 4>>>(w2, b2);
    conv3_mma<<<205, 256, C3_SMEM_ELEMS * 4>>>(w3, b3);
    conv4_kernel<<<dim3(16, 4, KZ4), 256>>>(w4);
    head_kernel<<<64, 256>>>(b4, enc_w, enc_b, sink_w, sink_b, mask_w, mask_b, out_stop);
    sinkhorn_kernel<<<64, 128>>>(gn, seq, out_ordered);
}

// round 16
// speedup vs baseline: 1.0382x; 1.0382x over previous
#include <cuda_runtime.h>
#include <cuda_bf16.h>
#include <cstdint>

// ---------------- problem constants ----------------
#define BATCH   1024
#define NSAMP   8
#define KDIM    6
#define NITERS  20
#define KZ4     10          // conv4 split-K factor

// ---------------- scratch (device globals; no allocs allowed) ----------------
__device__ float g_act1[BATCH * 32 * 30 * 30];
__device__ float g_act2[BATCH * 64 * 13 * 13];
__device__ float g_act3[BATCH * 128 * 5 * 5];
__device__ float g_featp[KZ4 * BATCH * 256];
__device__ float g_logalpha[BATCH * 36];

// ============================================================================
// helpers
// ============================================================================
__device__ __forceinline__ uint32_t f2tf32(float f) {
    uint32_t r;
    asm("cvt.rna.tf32.f32 %0, %1;" : "=r"(r) : "f"(f));
    return r;
}
// m16n8k8 tf32 row.col, fp32 accum in place
__device__ __forceinline__ void mma_tf32(float* d, const uint32_t* a, const uint32_t* b) {
    asm volatile(
        "mma.sync.aligned.m16n8k8.row.col.f32.tf32.tf32.f32 "
        "{%0,%1,%2,%3}, {%4,%5,%6,%7}, {%8,%9}, {%0,%1,%2,%3};"
        : "+f"(d[0]), "+f"(d[1]), "+f"(d[2]), "+f"(d[3])
        : "r"(a[0]), "r"(a[1]), "r"(a[2]), "r"(a[3]), "r"(b[0]), "r"(b[1]));
}

// fragment pitch 60: 60g mod 32 = {0,28,24,20,16,12,8,4}; +tq(0..3) fills the
// 4-gaps disjointly -> conflict-free (verified win in R12).
#define PITCH 60

// no-op kernel: shifts the ncu profiled-launch slot (our 4th launch) onto conv1
__global__ void noop_kernel() {}

// ============================================================================
// conv1 (scalar fp32, proven): [B,3,64,64] -> [B,32,30,30]. 16 oc/CTA.
// ============================================================================
__global__ __launch_bounds__(256, 2) void conv1_kernel(
    const float* __restrict__ im, const float* __restrict__ w1,
    const float* __restrict__ b1)
{
    __shared__ float s_in[64 * 64];
    __shared__ float s_w[16 * 75];

    const int b   = blockIdx.x;
    const int oc0 = blockIdx.y * 16;
    const int t   = threadIdx.x;

    for (int i = t; i < 1200; i += 256) s_w[i] = w1[oc0 * 75 + i];

    float acc[4][16];
#pragma unroll
    for (int i = 0; i < 4; i++)
#pragma unroll
        for (int o = 0; o < 16; o++) acc[i][o] = 0.f;

    int bo[4]; bool val[4];
#pragma unroll
    for (int i = 0; i < 4; i++) {
        int p = t + 256 * i;
        val[i] = (p < 900);
        int oy = p / 30, ox = p % 30;
        bo[i] = val[i] ? (2 * oy * 64 + 2 * ox) : 0;
    }

#pragma unroll 1
    for (int c = 0; c < 3; c++) {
        __syncthreads();
        const float4* src = reinterpret_cast<const float4*>(im + (b * 3 + c) * 4096);
        float4* dst = reinterpret_cast<float4*>(s_in);
        for (int e = t; e < 1024; e += 256) dst[e] = src[e];
        __syncthreads();

#pragma unroll 1
        for (int ky = 0; ky < 5; ky++) {
#pragma unroll
            for (int kx = 0; kx < 5; kx++) {
                float w16[16];
#pragma unroll
                for (int o = 0; o < 16; o++)
                    w16[o] = s_w[o * 75 + c * 25 + ky * 5 + kx];
#pragma unroll
                for (int i = 0; i < 4; i++) {
                    float v = s_in[bo[i] + ky * 64 + kx];
#pragma unroll
                    for (int o = 0; o < 16; o++) acc[i][o] += v * w16[o];
                }
            }
        }
    }

#pragma unroll
    for (int o = 0; o < 16; o++) {
        float bias = b1[oc0 + o];
#pragma unroll
        for (int i = 0; i < 4; i++) {
            int p = t + 256 * i;
            if (val[i])
                g_act1[(b * 32 + oc0 + o) * 900 + p] = fmaxf(acc[i][o] + bias, 0.f);
        }
    }
}

// ============================================================================
// conv2 via tf32 mma.sync (exact R12 best): 2 ch/chunk (K=56, 7 k8-steps),
// 16 chunks. grid 1024, block 256 (8 warps = 4m x 2n; warp tile 48x32).
// smem (u32): A[192*60] B[64*60] ph[1800] = 68640 B  (opt-in)
// ============================================================================
#define C2_A  0
#define C2_B  (192*PITCH)               // 11520
#define C2_P  (C2_B + 64*PITCH)         // 15360
#define C2_SMEM_ELEMS (C2_P + 1800)     // 17160 u32 = 68640 B

__global__ __launch_bounds__(256, 2) void conv2_mma(
    const float* __restrict__ w2, const float* __restrict__ b2)
{
    extern __shared__ uint32_t s2[];
    uint32_t* A  = s2 + C2_A;
    uint32_t* B  = s2 + C2_B;
    uint32_t* ph = s2 + C2_P;

    const int b = blockIdx.x, t = threadIdx.x;
    const int wid = t >> 5, lane = t & 31, g = lane >> 2, tq = lane & 3;
    const int wm = wid >> 1, wn = wid & 1;   // 4m x 2n

    // zero A+B once (pad rows + slots 50..59 stay 0)
    for (int i = t; i < C2_P; i += 256) s2[i] = 0u;

    float acc[3][4][4];
#pragma unroll
    for (int mt = 0; mt < 3; mt++)
#pragma unroll
        for (int nt = 0; nt < 4; nt++)
#pragma unroll
            for (int i = 0; i < 4; i++) acc[mt][nt][i] = 0.f;

    const float* src = g_act1 + b * 32 * 900;   // chunk = 1800 contiguous floats
    float4 pf0 = make_float4(0.f,0.f,0.f,0.f), pf1 = pf0;
    if (t < 225) {
        pf0 = reinterpret_cast<const float4*>(src)[t];
        pf1 = reinterpret_cast<const float4*>(src)[t + 225];
    }

#pragma unroll 1
    for (int cc = 0; cc < 16; cc++) {
        if (t < 225) {
            ph[4*t+0] = f2tf32(pf0.x); ph[4*t+1] = f2tf32(pf0.y);
            ph[4*t+2] = f2tf32(pf0.z); ph[4*t+3] = f2tf32(pf0.w);
            const int u = 4 * (t + 225);
            ph[u+0] = f2tf32(pf1.x); ph[u+1] = f2tf32(pf1.y);
            ph[u+2] = f2tf32(pf1.z); ph[u+3] = f2tf32(pf1.w);
        }
        __syncthreads();

        if (cc + 1 < 16 && t < 225) {
            const float4* nsrc = reinterpret_cast<const float4*>(src + (cc + 1) * 1800);
            pf0 = nsrc[t];
            pf1 = nsrc[t + 225];
        }

        // A build (t<169): u32 smem->smem im2col, 2 channels
        if (t < 169) {
            const int ib = (t / 13) * 60 + (t % 13) * 2;
            uint32_t* Arow = &A[t * PITCH];
#pragma unroll
            for (int c2 = 0; c2 < 2; c2++)
#pragma unroll
                for (int k = 0; k < 25; k++)
                    Arow[c2 * 25 + k] = ph[c2 * 900 + ib + (k / 5) * 30 + (k % 5)];
        } else if (t < 233) {
            const int oc = t - 169;
            const float* ws = w2 + oc * 800 + cc * 50;   // 50 contiguous floats
            uint32_t* Brow = &B[oc * PITCH];
#pragma unroll
            for (int k = 0; k < 50; k++)
                Brow[k] = f2tf32(ws[k]);
        }
        __syncthreads();

#pragma unroll
        for (int ks = 0; ks < 7; ks++) {
            const int kc = ks * 8 + tq;
            uint32_t a[3][4], bb[4][2];
#pragma unroll
            for (int mt = 0; mt < 3; mt++) {
                const int r = wm * 48 + mt * 16;
                a[mt][0] = A[(r + g) * PITCH + kc];
                a[mt][1] = A[(r + g + 8) * PITCH + kc];
                a[mt][2] = A[(r + g) * PITCH + kc + 4];
                a[mt][3] = A[(r + g + 8) * PITCH + kc + 4];
            }
#pragma unroll
            for (int nt = 0; nt < 4; nt++) {
                const int n = wn * 32 + nt * 8 + g;
                bb[nt][0] = B[n * PITCH + kc];
                bb[nt][1] = B[n * PITCH + kc + 4];
            }
#pragma unroll
            for (int mt = 0; mt < 3; mt++)
#pragma unroll
                for (int nt = 0; nt < 4; nt++)
                    mma_tf32(acc[mt][nt], a[mt], bb[nt]);
        }
        __syncthreads();
    }

    float* dst = g_act2 + b * 64 * 169;
#pragma unroll
    for (int mt = 0; mt < 3; mt++) {
        const int r0 = wm * 48 + mt * 16 + g;
        const int r1 = r0 + 8;
#pragma unroll
        for (int nt = 0; nt < 4; nt++) {
            const int n0 = wn * 32 + nt * 8 + 2 * tq;
            const float bi0 = b2[n0], bi1 = b2[n0 + 1];
            if (r0 < 169) {
                dst[n0 * 169 + r0]       = fmaxf(acc[mt][nt][0] + bi0, 0.f);
                dst[(n0 + 1) * 169 + r0] = fmaxf(acc[mt][nt][1] + bi1, 0.f);
            }
            if (r1 < 169) {
                dst[n0 * 169 + r1]       = fmaxf(acc[mt][nt][2] + bi0, 0.f);
                dst[(n0 + 1) * 169 + r1] = fmaxf(acc[mt][nt][3] + bi1, 0.f);
            }
        }
    }
}

// ============================================================================
// conv3 via tf32 mma.sync (exact R12 best), 2 ch/chunk. 5 images/CTA.
// grid 205, block 256 (8 warps = 2m x 4n; warp tile 64x32). 32 chunks.
// smem (u32): A[128*60] B[128*60] ph[1690] = 68200 B  (opt-in)
// ============================================================================
#define C3_A  0
#define C3_B  (128*PITCH)               // 7680
#define C3_P  (C3_B + 128*PITCH)        // 15360
#define C3_SMEM_ELEMS (C3_P + 1690)     // 17050 u32 = 68200 B

__global__ __launch_bounds__(256, 2) void conv3_mma(
    const float* __restrict__ w3, const float* __restrict__ b3)
{
    extern __shared__ uint32_t s3[];
    uint32_t* A  = s3 + C3_A;
    uint32_t* B  = s3 + C3_B;
    uint32_t* ph = s3 + C3_P;

    const int t = threadIdx.x;
    const int wid = t >> 5, lane = t & 31, g = lane >> 2, tq = lane & 3;
    const int wm = wid >> 2, wn = wid & 3;   // 2m x 4n
    const int b0 = blockIdx.x * 5;
    const int nimg = (BATCH - b0 < 5) ? (BATCH - b0) : 5;

    for (int i = t; i < C3_P; i += 256) s3[i] = 0u;

    float acc[4][4][4];
#pragma unroll
    for (int mt = 0; mt < 4; mt++)
#pragma unroll
        for (int nt = 0; nt < 4; nt++)
#pragma unroll
            for (int i = 0; i < 4; i++) acc[mt][nt][i] = 0.f;

    // prefetch chunk 0 planes: 1690 floats (5 img x 2 ch x 169)
    float pf[7];
    int pfil[7], pfc2[7], pfidx[7]; bool pfv[7];
#pragma unroll
    for (int k = 0; k < 7; k++) {
        const int i = t + 256 * k;
        pfv[k]   = (i < 1690);
        const int il = pfv[k] ? (i / 338) : 0;
        const int r  = pfv[k] ? (i % 338) : 0;
        pfil[k]  = il;
        pfc2[k]  = r / 169;
        pfidx[k] = r % 169;
        pfv[k]   = pfv[k] && (il < nimg);
        pf[k] = pfv[k] ? g_act2[((b0 + il) * 64 + pfc2[k]) * 169 + pfidx[k]] : 0.f;
    }

#pragma unroll 1
    for (int cc = 0; cc < 32; cc++) {
#pragma unroll
        for (int k = 0; k < 7; k++) {
            const int i = t + 256 * k;
            if (i < 1690) ph[i] = f2tf32(pf[k]);
        }
        __syncthreads();

        if (cc + 1 < 32) {
#pragma unroll
            for (int k = 0; k < 7; k++)
                if (pfv[k])
                    pf[k] = g_act2[((b0 + pfil[k]) * 64 + (cc + 1) * 2 + pfc2[k]) * 169 + pfidx[k]];
        }

        if (t < 125) {
            const int il = t / 25, p = t % 25;
            if (il < nimg) {
                const int pb = (p / 5) * 26 + (p % 5) * 2;
                uint32_t* Arow = &A[t * PITCH];
#pragma unroll
                for (int c2 = 0; c2 < 2; c2++)
#pragma unroll
                    for (int k = 0; k < 25; k++)
                        Arow[c2 * 25 + k] =
                            ph[il * 338 + c2 * 169 + pb + (k / 5) * 13 + (k % 5)];
            }
        } else if (t < 253) {
            const int oc = t - 125;
            const float* ws = w3 + oc * 1600 + cc * 50;   // 50 contiguous
            uint32_t* Brow = &B[oc * PITCH];
#pragma unroll
            for (int k = 0; k < 50; k++)
                Brow[k] = f2tf32(ws[k]);
        }
        __syncthreads();

#pragma unroll
        for (int ks = 0; ks < 7; ks++) {
            const int kc = ks * 8 + tq;
            uint32_t a[4][4], bb[4][2];
#pragma unroll
            for (int mt = 0; mt < 4; mt++) {
                const int r = wm * 64 + mt * 16;
                a[mt][0] = A[(r + g) * PITCH + kc];
                a[mt][1] = A[(r + g + 8) * PITCH + kc];
                a[mt][2] = A[(r + g) * PITCH + kc + 4];
                a[mt][3] = A[(r + g + 8) * PITCH + kc + 4];
            }
#pragma unroll
            for (int nt = 0; nt < 4; nt++) {
                const int n = wn * 32 + nt * 8 + g;
                bb[nt][0] = B[n * PITCH + kc];
                bb[nt][1] = B[n * PITCH + kc + 4];
            }
#pragma unroll
            for (int mt = 0; mt < 4; mt++)
#pragma unroll
                for (int nt = 0; nt < 4; nt++)
                    mma_tf32(acc[mt][nt], a[mt], bb[nt]);
        }
        __syncthreads();
    }

#pragma unroll
    for (int mt = 0; mt < 4; mt++) {
#pragma unroll
        for (int nt = 0; nt < 4; nt++) {
            const int n0 = wn * 32 + nt * 8 + 2 * tq;
            const float bi0 = b3[n0], bi1 = b3[n0 + 1];
#pragma unroll
            for (int half = 0; half < 2; half++) {
                const int r = wm * 64 + mt * 16 + g + half * 8;
                if (r < 125) {
                    const int il = r / 25, pp = r % 25;
                    if (il < nimg) {
                        float* o = g_act3 + ((b0 + il) * 128) * 25 + pp;
                        o[n0 * 25]       = fmaxf(acc[mt][nt][half * 2 + 0] + bi0, 0.f);
                        o[(n0 + 1) * 25] = fmaxf(acc[mt][nt][half * 2 + 1] + bi1, 0.f);
                    }
                }
            }
        }
    }
}

// ============================================================================
// conv4: split-K x10 scalar GEMM partials. grid (16,4,10), chunk 320.
// ============================================================================
__global__ __launch_bounds__(256) void conv4_kernel(
    const float* __restrict__ w4)
{
    __shared__ float s_a[32 * 68];
    __shared__ float s_w[32 * 68];

    const int bm = blockIdx.x * 64;
    const int bn = blockIdx.y * 64;
    const int kz = blockIdx.z;
    const int t  = threadIdx.x;
    const int tx = t & 15;
    const int ty = t >> 4;

    const float* Ag = g_act3;

    float acc[4][4];
#pragma unroll
    for (int i = 0; i < 4; i++)
#pragma unroll
        for (int j = 0; j < 4; j++) acc[i][j] = 0.f;

#pragma unroll 1
    for (int k0 = kz * 320; k0 < kz * 320 + 320; k0 += 32) {
        __syncthreads();
        for (int e = t; e < 2048; e += 256) {
            int r = e >> 5, kk = e & 31;
            s_a[kk * 68 + r] = Ag[(bm + r) * 3200 + k0 + kk];
            s_w[kk * 68 + r] = w4[(bn + r) * 3200 + k0 + kk];
        }
        __syncthreads();

#pragma unroll 4
        for (int kk = 0; kk < 32; kk++) {
            float4 av = *reinterpret_cast<const float4*>(&s_a[kk * 68 + ty * 4]);
            float4 wv = *reinterpret_cast<const float4*>(&s_w[kk * 68 + tx * 4]);
            float a[4] = {av.x, av.y, av.z, av.w};
            float w[4] = {wv.x, wv.y, wv.z, wv.w};
#pragma unroll
            for (int i = 0; i < 4; i++)
#pragma unroll
                for (int j = 0; j < 4; j++) acc[i][j] += a[i] * w[j];
        }
    }

    float* dst = g_featp + kz * (BATCH * 256);
#pragma unroll
    for (int i = 0; i < 4; i++)
#pragma unroll
        for (int j = 0; j < 4; j++)
            dst[(bm + ty * 4 + i) * 256 + (bn + tx * 4 + j)] = acc[i][j];
}

// ============================================================================
// head: feat = relu(sum_z partials + b4); latent; log_alpha; stopping softmax
// ============================================================================
__global__ __launch_bounds__(256) void head_kernel(
    const float* __restrict__ b4,
    const float* __restrict__ enc_w, const float* __restrict__ enc_b,
    const float* __restrict__ sink_w, const float* __restrict__ sink_b,
    const float* __restrict__ mask_w, const float* __restrict__ mask_b,
    float* __restrict__ out_stop)
{
    __shared__ float s_encw[16 * 257];
    __shared__ float s_feat[16][256];
    __shared__ float s_sw[576], s_sb[36], s_mw[96], s_mb[6];
    __shared__ float s_lat[16][16];

    const int t  = threadIdx.x;
    const int b0 = blockIdx.x * 16;

    for (int e = t; e < 4096; e += 256) {
        int l = e >> 8, i = e & 255;
        s_encw[l * 257 + i] = enc_w[e];
        float v = b4[i];
#pragma unroll
        for (int z = 0; z < KZ4; z++)
            v += g_featp[z * (BATCH * 256) + (b0 + l) * 256 + i];
        s_feat[l][i] = fmaxf(v, 0.f);
    }
    for (int e = t; e < 576; e += 256) s_sw[e] = sink_w[e];
    if (t < 36) s_sb[t] = sink_b[t];
    for (int e = t; e < 96; e += 256) s_mw[e] = mask_w[e];
    if (t < 6) s_mb[t] = mask_b[t];
    __syncthreads();

    const int bl = t >> 4;
    const int l  = t & 15;
    const int b  = b0 + bl;

    float lat = enc_b[l];
#pragma unroll 8
    for (int i = 0; i < 256; i++)
        lat += s_feat[bl][i] * s_encw[l * 257 + i];
    s_lat[bl][l] = lat;
    __syncthreads();

    for (int rr = l; rr < 36; rr += 16) {
        float la = s_sb[rr];
#pragma unroll
        for (int i = 0; i < 16; i++) la += s_lat[bl][i] * s_sw[rr * 16 + i];
        g_logalpha[b * 36 + rr] = la;
    }

    if (l == 0) {
        float lg[6];
        float mx = -1e30f;
#pragma unroll
        for (int k = 0; k < 6; k++) {
            float v = s_mb[k];
#pragma unroll
            for (int i = 0; i < 16; i++) v += s_lat[bl][i] * s_mw[k * 16 + i];
            lg[k] = v;
            mx = fmaxf(mx, v);
        }
        float sum = 0.f;
#pragma unroll
        for (int k = 0; k < 6; k++) { lg[k] = __expf(lg[k] - mx); sum += lg[k]; }
        float inv = 1.f / sum;
#pragma unroll
        for (int k = 0; k < 6; k++) out_stop[b * 6 + k] = lg[k] * inv;
    }
}

// ============================================================================
// sinkhorn: one thread per 6x6 matrix, grid 64 x block 128
// ============================================================================
__global__ __launch_bounds__(128) void sinkhorn_kernel(
    const float* __restrict__ gn, const float* __restrict__ seq,
    float* __restrict__ out_ordered)
{
    const int m = blockIdx.x * 128 + threadIdx.x;
    const int b = m & (BATCH - 1);

    float la[36];
#pragma unroll
    for (int i = 0; i < 36; i++)
        la[i] = g_logalpha[b * 36 + i] + gn[m * 36 + i];

    float sq[6];
#pragma unroll
    for (int j = 0; j < 6; j++) sq[j] = seq[b * 6 + j];

#pragma unroll 1
    for (int it = 0; it < NITERS; it++) {
#pragma unroll
        for (int j = 0; j < 6; j++) {
            float mx = la[j * 6];
#pragma unroll
            for (int k = 1; k < 6; k++) mx = fmaxf(mx, la[j * 6 + k]);
            float s = 0.f;
#pragma unroll
            for (int k = 0; k < 6; k++) s += __expf(la[j * 6 + k] - mx);
            float lse = mx + __logf(s);
#pragma unroll
            for (int k = 0; k < 6; k++) la[j * 6 + k] -= lse;
        }
#pragma unroll
        for (int k = 0; k < 6; k++) {
            float mx = la[k];
#pragma unroll
            for (int j = 1; j < 6; j++) mx = fmaxf(mx, la[j * 6 + k]);
            float s = 0.f;
#pragma unroll
            for (int j = 0; j < 6; j++) s += __expf(la[j * 6 + k] - mx);
            float lse = mx + __logf(s);
#pragma unroll
            for (int j = 0; j < 6; j++) la[j * 6 + k] -= lse;
        }
    }

#pragma unroll
    for (int k = 0; k < 6; k++) {
        float o = 0.f;
#pragma unroll
        for (int j = 0; j < 6; j++) o += __expf(la[j * 6 + k]) * sq[j];
        out_ordered[m * 6 + k] = o;
    }
}

// ============================================================================
extern "C" void kernel_launch(void* const* d_in, const int* in_sizes, int n_in,
                              void* d_out, int out_size)
{
    const float* seq    = (const float*)d_in[0];
    const float* im     = (const float*)d_in[1];
    const float* gn     = (const float*)d_in[2];
    const float* w1     = (const float*)d_in[3];
    const float* b1     = (const float*)d_in[4];
    const float* w2     = (const float*)d_in[5];
    const float* b2     = (const float*)d_in[6];
    const float* w3     = (const float*)d_in[7];
    const float* b3     = (const float*)d_in[8];
    const float* w4     = (const float*)d_in[9];
    const float* b4     = (const float*)d_in[10];
    const float* enc_w  = (const float*)d_in[11];
    const float* enc_b  = (const float*)d_in[12];
    const float* sink_w = (const float*)d_in[13];
    const float* sink_b = (const float*)d_in[14];
    const float* mask_w = (const float*)d_in[15];
    const float* mask_b = (const float*)d_in[16];

    float* out = (float*)d_out;
    float* out_ordered = out;                         // [8192*6]
    float* out_stop    = out + NSAMP * BATCH * KDIM;  // [1024*6]

    cudaFuncSetAttribute(conv2_mma, cudaFuncAttributeMaxDynamicSharedMemorySize,
                         C2_SMEM_ELEMS * 4);
    cudaFuncSetAttribute(conv3_mma, cudaFuncAttributeMaxDynamicSharedMemorySize,
                         C3_SMEM_ELEMS * 4);

    // three no-ops: the ncu profiled slot (our 4th launch) lands on conv1
    noop_kernel<<<1, 32>>>();
    noop_kernel<<<1, 32>>>();
    noop_kernel<<<1, 32>>>();
    conv1_kernel<<<dim3(BATCH, 2), 256>>>(im, w1, b1);
    conv2_mma<<<BATCH, 256, C2_SMEM_ELEMS * 4>>>(w2, b2);
    conv3_mma<<<205, 256, C3_SMEM_ELEMS * 4>>>(w3, b3);
    conv4_kernel<<<dim3(16, 4, KZ4), 256>>>(w4);
    head_kernel<<<64, 256>>>(b4, enc_w, enc_b, sink_w, sink_b, mask_w, mask_b, out_stop);
    sinkhorn_kernel<<<64, 128>>>(gn, seq, out_ordered);
}

// round 17
// speedup vs baseline: 1.0854x; 1.0455x over previous
#include <cuda_runtime.h>
#include <cuda_bf16.h>
#include <cstdint>

// ---------------- problem constants ----------------
#define BATCH   1024
#define NSAMP   8
#define KDIM    6
#define NITERS  20
#define KZ4     10          // conv4 split-K factor

// ---------------- scratch (device globals; no allocs allowed) ----------------
__device__ float g_act1[BATCH * 32 * 30 * 30];
__device__ float g_act2[BATCH * 64 * 13 * 13];
__device__ float g_act3[BATCH * 128 * 5 * 5];
__device__ float g_featp[KZ4 * BATCH * 256];
__device__ float g_logalpha[BATCH * 36];

// ============================================================================
// helpers
// ============================================================================
__device__ __forceinline__ uint32_t f2tf32(float f) {
    uint32_t r;
    asm("cvt.rna.tf32.f32 %0, %1;" : "=r"(r) : "f"(f));
    return r;
}
// m16n8k8 tf32 row.col, fp32 accum in place
__device__ __forceinline__ void mma_tf32(float* d, const uint32_t* a, const uint32_t* b) {
    asm volatile(
        "mma.sync.aligned.m16n8k8.row.col.f32.tf32.tf32.f32 "
        "{%0,%1,%2,%3}, {%4,%5,%6,%7}, {%8,%9}, {%0,%1,%2,%3};"
        : "+f"(d[0]), "+f"(d[1]), "+f"(d[2]), "+f"(d[3])
        : "r"(a[0]), "r"(a[1]), "r"(a[2]), "r"(a[3]), "r"(b[0]), "r"(b[1]));
}

// pitch 60 (conv2/conv3): conflict-free fragment loads (R12-verified)
#define PITCH 60
// pitch 84 (conv1): 84g mod 32 = 20g = {0,20,8,28,16,4,24,12}; +tq disjoint
#define PITCH1 84

// no-op kernel: keeps the ncu profiled-launch slot (4th launch) on conv1_mma
__global__ void noop_kernel() {}

// ============================================================================
// conv1 via tf32 mma.sync: [B,3,64,64] -> [B,32,30,30]
// grid (1024, 5): image b, M-tile of 180 positions (6 output rows).
// block 256 (8 warps = 4m x 2n; warp tile 48x16). SINGLE K-chunk:
// K = 3 ch x 25 taps = 75 -> pad 80 (10 k8-steps). No channel loop.
// smem (u32): A[192*84] B[32*84] plane[2880] = 86784 B (opt-in)
// A pad-cols (75..79) written 0 by build; A pad-rows (180..191) garbage but
// only feed discarded D rows; B pad slots written 0.
// ============================================================================
#define C1_A  0
#define C1_B  (192*PITCH1)               // 16128
#define C1_P  (C1_B + 32*PITCH1)         // 18816
#define C1_SMEM_ELEMS (C1_P + 2880)      // 21696 u32 = 86784 B

__global__ __launch_bounds__(256, 2) void conv1_mma(
    const float* __restrict__ im, const float* __restrict__ w1,
    const float* __restrict__ b1)
{
    extern __shared__ uint32_t s1[];
    uint32_t* A  = s1 + C1_A;
    uint32_t* B  = s1 + C1_B;
    uint32_t* ph = s1 + C1_P;

    const int b = blockIdx.x, tile = blockIdx.y, t = threadIdx.x;
    const int wid = t >> 5, lane = t & 31, g = lane >> 2, tq = lane & 3;
    const int wm = wid >> 1, wn = wid & 1;   // 4m x 2n

    // stage 15-row input window for 3 channels: 3 x 960 floats (240 float4/ch)
    const float* src = im + b * 3 * 4096 + 12 * tile * 64;
#pragma unroll
    for (int k = 0; k < 3; k++) {
        const int i = t + 256 * k;   // 0..719 float4 units
        if (i < 720) {
            const int ch = i / 240, e = i % 240;
            float4 v = reinterpret_cast<const float4*>(src + ch * 4096)[e];
            const int u = ch * 960 + 4 * e;
            ph[u+0] = f2tf32(v.x); ph[u+1] = f2tf32(v.y);
            ph[u+2] = f2tf32(v.z); ph[u+3] = f2tf32(v.w);
        }
    }
    __syncthreads();

    // A build (t<180): row t, 75 valid k-slots + 5 zeros
    if (t < 180) {
        const int ib = (t / 30) * 128 + (t % 30) * 2;
        uint32_t* Arow = &A[t * PITCH1];
#pragma unroll
        for (int ch = 0; ch < 3; ch++)
#pragma unroll
            for (int k = 0; k < 25; k++)
                Arow[ch * 25 + k] = ph[ch * 960 + ib + (k / 5) * 64 + (k % 5)];
#pragma unroll
        for (int k = 75; k < 80; k++) Arow[k] = 0u;
    } else if (t < 212) {
        // B build (32 oc): 75 contiguous weights + 5 zeros
        const int oc = t - 180;
        const float* ws = w1 + oc * 75;
        uint32_t* Brow = &B[oc * PITCH1];
#pragma unroll
        for (int k = 0; k < 75; k++) Brow[k] = f2tf32(ws[k]);
#pragma unroll
        for (int k = 75; k < 80; k++) Brow[k] = 0u;
    }
    __syncthreads();

    float acc[3][2][4];
#pragma unroll
    for (int mt = 0; mt < 3; mt++)
#pragma unroll
        for (int nt = 0; nt < 2; nt++)
#pragma unroll
            for (int i = 0; i < 4; i++) acc[mt][nt][i] = 0.f;

#pragma unroll
    for (int ks = 0; ks < 10; ks++) {
        const int kc = ks * 8 + tq;
        uint32_t a[3][4], bb[2][2];
#pragma unroll
        for (int mt = 0; mt < 3; mt++) {
            const int r = wm * 48 + mt * 16;
            a[mt][0] = A[(r + g) * PITCH1 + kc];
            a[mt][1] = A[(r + g + 8) * PITCH1 + kc];
            a[mt][2] = A[(r + g) * PITCH1 + kc + 4];
            a[mt][3] = A[(r + g + 8) * PITCH1 + kc + 4];
        }
#pragma unroll
        for (int nt = 0; nt < 2; nt++) {
            const int n = wn * 16 + nt * 8 + g;
            bb[nt][0] = B[n * PITCH1 + kc];
            bb[nt][1] = B[n * PITCH1 + kc + 4];
        }
#pragma unroll
        for (int mt = 0; mt < 3; mt++)
#pragma unroll
            for (int nt = 0; nt < 2; nt++)
                mma_tf32(acc[mt][nt], a[mt], bb[nt]);
    }

    // epilogue: bias + relu -> g_act1[b][oc][tile*180 + r]
#pragma unroll
    for (int mt = 0; mt < 3; mt++) {
#pragma unroll
        for (int nt = 0; nt < 2; nt++) {
            const int n0 = wn * 16 + nt * 8 + 2 * tq;
            const float bi0 = b1[n0], bi1 = b1[n0 + 1];
#pragma unroll
            for (int half = 0; half < 2; half++) {
                const int r = wm * 48 + mt * 16 + g + half * 8;
                if (r < 180) {
                    const int p = tile * 180 + r;
                    g_act1[(b * 32 + n0) * 900 + p] =
                        fmaxf(acc[mt][nt][half * 2 + 0] + bi0, 0.f);
                    g_act1[(b * 32 + n0 + 1) * 900 + p] =
                        fmaxf(acc[mt][nt][half * 2 + 1] + bi1, 0.f);
                }
            }
        }
    }
}

// ============================================================================
// conv2 via tf32 mma.sync (exact R12 best): 2 ch/chunk (K=56, 7 k8-steps),
// 16 chunks. grid 1024, block 256 (8 warps = 4m x 2n; warp tile 48x32).
// smem (u32): A[192*60] B[64*60] ph[1800] = 68640 B  (opt-in)
// ============================================================================
#define C2_A  0
#define C2_B  (192*PITCH)               // 11520
#define C2_P  (C2_B + 64*PITCH)         // 15360
#define C2_SMEM_ELEMS (C2_P + 1800)     // 17160 u32 = 68640 B

__global__ __launch_bounds__(256, 2) void conv2_mma(
    const float* __restrict__ w2, const float* __restrict__ b2)
{
    extern __shared__ uint32_t s2[];
    uint32_t* A  = s2 + C2_A;
    uint32_t* B  = s2 + C2_B;
    uint32_t* ph = s2 + C2_P;

    const int b = blockIdx.x, t = threadIdx.x;
    const int wid = t >> 5, lane = t & 31, g = lane >> 2, tq = lane & 3;
    const int wm = wid >> 1, wn = wid & 1;   // 4m x 2n

    for (int i = t; i < C2_P; i += 256) s2[i] = 0u;

    float acc[3][4][4];
#pragma unroll
    for (int mt = 0; mt < 3; mt++)
#pragma unroll
        for (int nt = 0; nt < 4; nt++)
#pragma unroll
            for (int i = 0; i < 4; i++) acc[mt][nt][i] = 0.f;

    const float* src = g_act1 + b * 32 * 900;
    float4 pf0 = make_float4(0.f,0.f,0.f,0.f), pf1 = pf0;
    if (t < 225) {
        pf0 = reinterpret_cast<const float4*>(src)[t];
        pf1 = reinterpret_cast<const float4*>(src)[t + 225];
    }

#pragma unroll 1
    for (int cc = 0; cc < 16; cc++) {
        if (t < 225) {
            ph[4*t+0] = f2tf32(pf0.x); ph[4*t+1] = f2tf32(pf0.y);
            ph[4*t+2] = f2tf32(pf0.z); ph[4*t+3] = f2tf32(pf0.w);
            const int u = 4 * (t + 225);
            ph[u+0] = f2tf32(pf1.x); ph[u+1] = f2tf32(pf1.y);
            ph[u+2] = f2tf32(pf1.z); ph[u+3] = f2tf32(pf1.w);
        }
        __syncthreads();

        if (cc + 1 < 16 && t < 225) {
            const float4* nsrc = reinterpret_cast<const float4*>(src + (cc + 1) * 1800);
            pf0 = nsrc[t];
            pf1 = nsrc[t + 225];
        }

        if (t < 169) {
            const int ib = (t / 13) * 60 + (t % 13) * 2;
            uint32_t* Arow = &A[t * PITCH];
#pragma unroll
            for (int c2 = 0; c2 < 2; c2++)
#pragma unroll
                for (int k = 0; k < 25; k++)
                    Arow[c2 * 25 + k] = ph[c2 * 900 + ib + (k / 5) * 30 + (k % 5)];
        } else if (t < 233) {
            const int oc = t - 169;
            const float* ws = w2 + oc * 800 + cc * 50;
            uint32_t* Brow = &B[oc * PITCH];
#pragma unroll
            for (int k = 0; k < 50; k++)
                Brow[k] = f2tf32(ws[k]);
        }
        __syncthreads();

#pragma unroll
        for (int ks = 0; ks < 7; ks++) {
            const int kc = ks * 8 + tq;
            uint32_t a[3][4], bb[4][2];
#pragma unroll
            for (int mt = 0; mt < 3; mt++) {
                const int r = wm * 48 + mt * 16;
                a[mt][0] = A[(r + g) * PITCH + kc];
                a[mt][1] = A[(r + g + 8) * PITCH + kc];
                a[mt][2] = A[(r + g) * PITCH + kc + 4];
                a[mt][3] = A[(r + g + 8) * PITCH + kc + 4];
            }
#pragma unroll
            for (int nt = 0; nt < 4; nt++) {
                const int n = wn * 32 + nt * 8 + g;
                bb[nt][0] = B[n * PITCH + kc];
                bb[nt][1] = B[n * PITCH + kc + 4];
            }
#pragma unroll
            for (int mt = 0; mt < 3; mt++)
#pragma unroll
                for (int nt = 0; nt < 4; nt++)
                    mma_tf32(acc[mt][nt], a[mt], bb[nt]);
        }
        __syncthreads();
    }

    float* dst = g_act2 + b * 64 * 169;
#pragma unroll
    for (int mt = 0; mt < 3; mt++) {
        const int r0 = wm * 48 + mt * 16 + g;
        const int r1 = r0 + 8;
#pragma unroll
        for (int nt = 0; nt < 4; nt++) {
            const int n0 = wn * 32 + nt * 8 + 2 * tq;
            const float bi0 = b2[n0], bi1 = b2[n0 + 1];
            if (r0 < 169) {
                dst[n0 * 169 + r0]       = fmaxf(acc[mt][nt][0] + bi0, 0.f);
                dst[(n0 + 1) * 169 + r0] = fmaxf(acc[mt][nt][1] + bi1, 0.f);
            }
            if (r1 < 169) {
                dst[n0 * 169 + r1]       = fmaxf(acc[mt][nt][2] + bi0, 0.f);
                dst[(n0 + 1) * 169 + r1] = fmaxf(acc[mt][nt][3] + bi1, 0.f);
            }
        }
    }
}

// ============================================================================
// conv3 via tf32 mma.sync (exact R12 best), 2 ch/chunk. 5 images/CTA.
// grid 205, block 256 (8 warps = 2m x 4n; warp tile 64x32). 32 chunks.
// smem (u32): A[128*60] B[128*60] ph[1690] = 68200 B  (opt-in)
// ============================================================================
#define C3_A  0
#define C3_B  (128*PITCH)               // 7680
#define C3_P  (C3_B + 128*PITCH)        // 15360
#define C3_SMEM_ELEMS (C3_P + 1690)     // 17050 u32 = 68200 B

__global__ __launch_bounds__(256, 2) void conv3_mma(
    const float* __restrict__ w3, const float* __restrict__ b3)
{
    extern __shared__ uint32_t s3[];
    uint32_t* A  = s3 + C3_A;
    uint32_t* B  = s3 + C3_B;
    uint32_t* ph = s3 + C3_P;

    const int t = threadIdx.x;
    const int wid = t >> 5, lane = t & 31, g = lane >> 2, tq = lane & 3;
    const int wm = wid >> 2, wn = wid & 3;   // 2m x 4n
    const int b0 = blockIdx.x * 5;
    const int nimg = (BATCH - b0 < 5) ? (BATCH - b0) : 5;

    for (int i = t; i < C3_P; i += 256) s3[i] = 0u;

    float acc[4][4][4];
#pragma unroll
    for (int mt = 0; mt < 4; mt++)
#pragma unroll
        for (int nt = 0; nt < 4; nt++)
#pragma unroll
            for (int i = 0; i < 4; i++) acc[mt][nt][i] = 0.f;

    float pf[7];
    int pfil[7], pfc2[7], pfidx[7]; bool pfv[7];
#pragma unroll
    for (int k = 0; k < 7; k++) {
        const int i = t + 256 * k;
        pfv[k]   = (i < 1690);
        const int il = pfv[k] ? (i / 338) : 0;
        const int r  = pfv[k] ? (i % 338) : 0;
        pfil[k]  = il;
        pfc2[k]  = r / 169;
        pfidx[k] = r % 169;
        pfv[k]   = pfv[k] && (il < nimg);
        pf[k] = pfv[k] ? g_act2[((b0 + il) * 64 + pfc2[k]) * 169 + pfidx[k]] : 0.f;
    }

#pragma unroll 1
    for (int cc = 0; cc < 32; cc++) {
#pragma unroll
        for (int k = 0; k < 7; k++) {
            const int i = t + 256 * k;
            if (i < 1690) ph[i] = f2tf32(pf[k]);
        }
        __syncthreads();

        if (cc + 1 < 32) {
#pragma unroll
            for (int k = 0; k < 7; k++)
                if (pfv[k])
                    pf[k] = g_act2[((b0 + pfil[k]) * 64 + (cc + 1) * 2 + pfc2[k]) * 169 + pfidx[k]];
        }

        if (t < 125) {
            const int il = t / 25, p = t % 25;
            if (il < nimg) {
                const int pb = (p / 5) * 26 + (p % 5) * 2;
                uint32_t* Arow = &A[t * PITCH];
#pragma unroll
                for (int c2 = 0; c2 < 2; c2++)
#pragma unroll
                    for (int k = 0; k < 25; k++)
                        Arow[c2 * 25 + k] =
                            ph[il * 338 + c2 * 169 + pb + (k / 5) * 13 + (k % 5)];
            }
        } else if (t < 253) {
            const int oc = t - 125;
            const float* ws = w3 + oc * 1600 + cc * 50;
            uint32_t* Brow = &B[oc * PITCH];
#pragma unroll
            for (int k = 0; k < 50; k++)
                Brow[k] = f2tf32(ws[k]);
        }
        __syncthreads();

#pragma unroll
        for (int ks = 0; ks < 7; ks++) {
            const int kc = ks * 8 + tq;
            uint32_t a[4][4], bb[4][2];
#pragma unroll
            for (int mt = 0; mt < 4; mt++) {
                const int r = wm * 64 + mt * 16;
                a[mt][0] = A[(r + g) * PITCH + kc];
                a[mt][1] = A[(r + g + 8) * PITCH + kc];
                a[mt][2] = A[(r + g) * PITCH + kc + 4];
                a[mt][3] = A[(r + g + 8) * PITCH + kc + 4];
            }
#pragma unroll
            for (int nt = 0; nt < 4; nt++) {
                const int n = wn * 32 + nt * 8 + g;
                bb[nt][0] = B[n * PITCH + kc];
                bb[nt][1] = B[n * PITCH + kc + 4];
            }
#pragma unroll
            for (int mt = 0; mt < 4; mt++)
#pragma unroll
                for (int nt = 0; nt < 4; nt++)
                    mma_tf32(acc[mt][nt], a[mt], bb[nt]);
        }
        __syncthreads();
    }

#pragma unroll
    for (int mt = 0; mt < 4; mt++) {
#pragma unroll
        for (int nt = 0; nt < 4; nt++) {
            const int n0 = wn * 32 + nt * 8 + 2 * tq;
            const float bi0 = b3[n0], bi1 = b3[n0 + 1];
#pragma unroll
            for (int half = 0; half < 2; half++) {
                const int r = wm * 64 + mt * 16 + g + half * 8;
                if (r < 125) {
                    const int il = r / 25, pp = r % 25;
                    if (il < nimg) {
                        float* o = g_act3 + ((b0 + il) * 128) * 25 + pp;
                        o[n0 * 25]       = fmaxf(acc[mt][nt][half * 2 + 0] + bi0, 0.f);
                        o[(n0 + 1) * 25] = fmaxf(acc[mt][nt][half * 2 + 1] + bi1, 0.f);
                    }
                }
            }
        }
    }
}

// ============================================================================
// conv4: split-K x10 scalar GEMM partials. grid (16,4,10), chunk 320.
// ============================================================================
__global__ __launch_bounds__(256) void conv4_kernel(
    const float* __restrict__ w4)
{
    __shared__ float s_a[32 * 68];
    __shared__ float s_w[32 * 68];

    const int bm = blockIdx.x * 64;
    const int bn = blockIdx.y * 64;
    const int kz = blockIdx.z;
    const int t  = threadIdx.x;
    const int tx = t & 15;
    const int ty = t >> 4;

    const float* Ag = g_act3;

    float acc[4][4];
#pragma unroll
    for (int i = 0; i < 4; i++)
#pragma unroll
        for (int j = 0; j < 4; j++) acc[i][j] = 0.f;

#pragma unroll 1
    for (int k0 = kz * 320; k0 < kz * 320 + 320; k0 += 32) {
        __syncthreads();
        for (int e = t; e < 2048; e += 256) {
            int r = e >> 5, kk = e & 31;
            s_a[kk * 68 + r] = Ag[(bm + r) * 3200 + k0 + kk];
            s_w[kk * 68 + r] = w4[(bn + r) * 3200 + k0 + kk];
        }
        __syncthreads();

#pragma unroll 4
        for (int kk = 0; kk < 32; kk++) {
            float4 av = *reinterpret_cast<const float4*>(&s_a[kk * 68 + ty * 4]);
            float4 wv = *reinterpret_cast<const float4*>(&s_w[kk * 68 + tx * 4]);
            float a[4] = {av.x, av.y, av.z, av.w};
            float w[4] = {wv.x, wv.y, wv.z, wv.w};
#pragma unroll
            for (int i = 0; i < 4; i++)
#pragma unroll
                for (int j = 0; j < 4; j++) acc[i][j] += a[i] * w[j];
        }
    }

    float* dst = g_featp + kz * (BATCH * 256);
#pragma unroll
    for (int i = 0; i < 4; i++)
#pragma unroll
        for (int j = 0; j < 4; j++)
            dst[(bm + ty * 4 + i) * 256 + (bn + tx * 4 + j)] = acc[i][j];
}

// ============================================================================
// head: feat = relu(sum_z partials + b4); latent; log_alpha; stopping softmax
// ============================================================================
__global__ __launch_bounds__(256) void head_kernel(
    const float* __restrict__ b4,
    const float* __restrict__ enc_w, const float* __restrict__ enc_b,
    const float* __restrict__ sink_w, const float* __restrict__ sink_b,
    const float* __restrict__ mask_w, const float* __restrict__ mask_b,
    float* __restrict__ out_stop)
{
    __shared__ float s_encw[16 * 257];
    __shared__ float s_feat[16][256];
    __shared__ float s_sw[576], s_sb[36], s_mw[96], s_mb[6];
    __shared__ float s_lat[16][16];

    const int t  = threadIdx.x;
    const int b0 = blockIdx.x * 16;

    for (int e = t; e < 4096; e += 256) {
        int l = e >> 8, i = e & 255;
        s_encw[l * 257 + i] = enc_w[e];
        float v = b4[i];
#pragma unroll
        for (int z = 0; z < KZ4; z++)
            v += g_featp[z * (BATCH * 256) + (b0 + l) * 256 + i];
        s_feat[l][i] = fmaxf(v, 0.f);
    }
    for (int e = t; e < 576; e += 256) s_sw[e] = sink_w[e];
    if (t < 36) s_sb[t] = sink_b[t];
    for (int e = t; e < 96; e += 256) s_mw[e] = mask_w[e];
    if (t < 6) s_mb[t] = mask_b[t];
    __syncthreads();

    const int bl = t >> 4;
    const int l  = t & 15;
    const int b  = b0 + bl;

    float lat = enc_b[l];
#pragma unroll 8
    for (int i = 0; i < 256; i++)
        lat += s_feat[bl][i] * s_encw[l * 257 + i];
    s_lat[bl][l] = lat;
    __syncthreads();

    for (int rr = l; rr < 36; rr += 16) {
        float la = s_sb[rr];
#pragma unroll
        for (int i = 0; i < 16; i++) la += s_lat[bl][i] * s_sw[rr * 16 + i];
        g_logalpha[b * 36 + rr] = la;
    }

    if (l == 0) {
        float lg[6];
        float mx = -1e30f;
#pragma unroll
        for (int k = 0; k < 6; k++) {
            float v = s_mb[k];
#pragma unroll
            for (int i = 0; i < 16; i++) v += s_lat[bl][i] * s_mw[k * 16 + i];
            lg[k] = v;
            mx = fmaxf(mx, v);
        }
        float sum = 0.f;
#pragma unroll
        for (int k = 0; k < 6; k++) { lg[k] = __expf(lg[k] - mx); sum += lg[k]; }
        float inv = 1.f / sum;
#pragma unroll
        for (int k = 0; k < 6; k++) out_stop[b * 6 + k] = lg[k] * inv;
    }
}

// ============================================================================
// sinkhorn: one thread per 6x6 matrix, grid 64 x block 128
// ============================================================================
__global__ __launch_bounds__(128) void sinkhorn_kernel(
    const float* __restrict__ gn, const float* __restrict__ seq,
    float* __restrict__ out_ordered)
{
    const int m = blockIdx.x * 128 + threadIdx.x;
    const int b = m & (BATCH - 1);

    float la[36];
#pragma unroll
    for (int i = 0; i < 36; i++)
        la[i] = g_logalpha[b * 36 + i] + gn[m * 36 + i];

    float sq[6];
#pragma unroll
    for (int j = 0; j < 6; j++) sq[j] = seq[b * 6 + j];

#pragma unroll 1
    for (int it = 0; it < NITERS; it++) {
#pragma unroll
        for (int j = 0; j < 6; j++) {
            float mx = la[j * 6];
#pragma unroll
            for (int k = 1; k < 6; k++) mx = fmaxf(mx, la[j * 6 + k]);
            float s = 0.f;
#pragma unroll
            for (int k = 0; k < 6; k++) s += __expf(la[j * 6 + k] - mx);
            float lse = mx + __logf(s);
#pragma unroll
            for (int k = 0; k < 6; k++) la[j * 6 + k] -= lse;
        }
#pragma unroll
        for (int k = 0; k < 6; k++) {
            float mx = la[k];
#pragma unroll
            for (int j = 1; j < 6; j++) mx = fmaxf(mx, la[j * 6 + k]);
            float s = 0.f;
#pragma unroll
            for (int j = 0; j < 6; j++) s += __expf(la[j * 6 + k] - mx);
            float lse = mx + __logf(s);
#pragma unroll
            for (int j = 0; j < 6; j++) la[j * 6 + k] -= lse;
        }
    }

#pragma unroll
    for (int k = 0; k < 6; k++) {
        float o = 0.f;
#pragma unroll
        for (int j = 0; j < 6; j++) o += __expf(la[j * 6 + k]) * sq[j];
        out_ordered[m * 6 + k] = o;
    }
}

// ============================================================================
extern "C" void kernel_launch(void* const* d_in, const int* in_sizes, int n_in,
                              void* d_out, int out_size)
{
    const float* seq    = (const float*)d_in[0];
    const float* im     = (const float*)d_in[1];
    const float* gn     = (const float*)d_in[2];
    const float* w1     = (const float*)d_in[3];
    const float* b1     = (const float*)d_in[4];
    const float* w2     = (const float*)d_in[5];
    const float* b2     = (const float*)d_in[6];
    const float* w3     = (const float*)d_in[7];
    const float* b3     = (const float*)d_in[8];
    const float* w4     = (const float*)d_in[9];
    const float* b4     = (const float*)d_in[10];
    const float* enc_w  = (const float*)d_in[11];
    const float* enc_b  = (const float*)d_in[12];
    const float* sink_w = (const float*)d_in[13];
    const float* sink_b = (const float*)d_in[14];
    const float* mask_w = (const float*)d_in[15];
    const float* mask_b = (const float*)d_in[16];

    float* out = (float*)d_out;
    float* out_ordered = out;                         // [8192*6]
    float* out_stop    = out + NSAMP * BATCH * KDIM;  // [1024*6]

    cudaFuncSetAttribute(conv1_mma, cudaFuncAttributeMaxDynamicSharedMemorySize,
                         C1_SMEM_ELEMS * 4);
    cudaFuncSetAttribute(conv2_mma, cudaFuncAttributeMaxDynamicSharedMemorySize,
                         C2_SMEM_ELEMS * 4);
    cudaFuncSetAttribute(conv3_mma, cudaFuncAttributeMaxDynamicSharedMemorySize,
                         C3_SMEM_ELEMS * 4);

    // three no-ops: the ncu profiled slot (4th launch) lands on conv1_mma
    noop_kernel<<<1, 32>>>();
    noop_kernel<<<1, 32>>>();
    noop_kernel<<<1, 32>>>();
    conv1_mma<<<dim3(BATCH, 5), 256, C1_SMEM_ELEMS * 4>>>(im, w1, b1);
    conv2_mma<<<BATCH, 256, C2_SMEM_ELEMS * 4>>>(w2, b2);
    conv3_mma<<<205, 256, C3_SMEM_ELEMS * 4>>>(w3, b3);
    conv4_kernel<<<dim3(16, 4, KZ4), 256>>>(w4);
    head_kernel<<<64, 256>>>(b4, enc_w, enc_b, sink_w, sink_b, mask_w, mask_b, out_stop);
    sinkhorn_kernel<<<64, 128>>>(gn, seq, out_ordered);
}